// round 1
// baseline (speedup 1.0000x reference)
#include <cuda_runtime.h>
#include <math.h>

// ---------------- problem constants ----------------
#define BB   4
#define SS   512
#define HH   512
#define NHH  8
#define TT   3
#define DHH  64          // HH/NHH
#define DTS  170         // HH/TT
#define BS   (BB*SS)             // 2048
#define BSS  (BB*SS*SS)          // 1,048,576
#define EPS  1e-5f

// ---------------- scratch layout (floats) ----------------
#define OFF_MASK     ((size_t)0)                       // 3 * BSS
#define OFF_QKV      (OFF_MASK + (size_t)3*BSS)        // BS * 1536
#define OFF_SCORES   (OFF_QKV + (size_t)BS*1536)       // B*NH*S*S = 8,388,608
#define OFF_ATTNO    (OFF_SCORES + (size_t)BB*NHH*SS*SS) // BS*H
#define OFF_COMB     (OFF_ATTNO + (size_t)BS*HH)       // BS*1536
#define OFF_MACT     (OFF_COMB + (size_t)BS*1536)      // BS*H
#define OFF_WEIGHTED (OFF_MACT + (size_t)BS*HH)
#define OFF_SA       (OFF_WEIGHTED + (size_t)BS*HH)
#define OFF_H1       (OFF_SA + (size_t)BS*HH)
#define OFF_FF       (OFF_H1 + (size_t)BS*HH)          // BS*2048
#define OFF_FFO      (OFF_FF + (size_t)BS*2048)
#define OFF_H2       (OFF_FFO + (size_t)BS*HH)
#define OFF_OP       (OFF_H2 + (size_t)BS*HH)
#define SCRATCH_FLOATS (OFF_OP + (size_t)BS*HH)

__device__ float g_scratch[SCRATCH_FLOATS];

// ---------------- helpers ----------------
__device__ __forceinline__ float gelu_exact(float x) {
    return 0.5f * x * (1.0f + erff(x * 0.70710678118654752f));
}
__device__ __forceinline__ float warp_sum(float x) {
    #pragma unroll
    for (int o = 16; o > 0; o >>= 1) x += __shfl_xor_sync(0xffffffffu, x, o);
    return x;
}
__device__ __forceinline__ float warp_max(float x) {
    #pragma unroll
    for (int o = 16; o > 0; o >>= 1) x = fmaxf(x, __shfl_xor_sync(0xffffffffu, x, o));
    return x;
}

// ---------------- mask kernel ----------------
// one warp per (b,q,k); fused: time features -> 2xDTS encoder -> LN -> GELU -> mean
__global__ void mask_kernel(const float* __restrict__ ts,
                            const float* __restrict__ enc_W,
                            const float* __restrict__ enc_b,
                            const float* __restrict__ enc_g,
                            const float* __restrict__ enc_be,
                            float* __restrict__ masks)
{
    __shared__ float sW0[TT][DTS], sW1[TT][DTS], sB[TT][DTS], sG[TT][DTS], sBe[TT][DTS];
    for (int i = threadIdx.x; i < TT*DTS; i += blockDim.x) {
        int t = i / DTS, d = i % DTS;
        sW0[t][d] = enc_W[(t*2+0)*DTS + d];
        sW1[t][d] = enc_W[(t*2+1)*DTS + d];
        sB [t][d] = enc_b [i];
        sG [t][d] = enc_g [i];
        sBe[t][d] = enc_be[i];
    }
    __syncthreads();

    int lane = threadIdx.x & 31;
    int warp = (blockIdx.x * blockDim.x + threadIdx.x) >> 5;
    int nwarps = gridDim.x * (blockDim.x >> 5);

    for (int t = warp; t < BSS; t += nwarps) {
        int b = t >> 18;          // S*S = 2^18
        int q = (t >> 9) & 511;
        int k = t & 511;
        float dt = ts[(b << 9) + q] - ts[(b << 9) + k];
        float dir = (dt > 0.f) ? 1.f : ((dt < 0.f) ? -1.f : 0.f);
        float m0 = log1pf(fabsf(dt) * (1.f/3600.f));
        float magmul = 1.f;
        #pragma unroll
        for (int i = 0; i < TT; i++) {
            float mag = m0 * magmul;
            float e[6];
            float s = 0.f, ss = 0.f;
            #pragma unroll
            for (int j = 0; j < 6; j++) {
                int d = lane + 32*j;
                float v = 0.f;
                if (d < DTS) v = dir*sW0[i][d] + mag*sW1[i][d] + sB[i][d];
                e[j] = v;
                s += v; ss += v*v;
            }
            s  = warp_sum(s);
            ss = warp_sum(ss);
            float mean = s * (1.f/DTS);
            float var  = ss * (1.f/DTS) - mean*mean;
            float rs = rsqrtf(var + EPS);
            float gs = 0.f;
            #pragma unroll
            for (int j = 0; j < 6; j++) {
                int d = lane + 32*j;
                if (d < DTS) {
                    float y = (e[j] - mean) * rs * sG[i][d] + sBe[i][d];
                    gs += gelu_exact(y);
                }
            }
            gs = warp_sum(gs);
            if (lane == 0) masks[(size_t)i*BSS + t] = gs * (1.f/DTS);
            magmul *= 0.1f;
        }
    }
}

// ---------------- generic GEMM: C[M,N] = A[M,K] @ B[K,N] (+bias)(+gelu) ----------------
// requires M%64==0, N%64==0, K%16==0, lda%4==0
__global__ __launch_bounds__(256)
void gemm_nn(const float* __restrict__ A, int lda,
             const float* __restrict__ Bm, int ldb,
             const float* __restrict__ bias,
             float* __restrict__ C, int ldc,
             int K, int epi)
{
    __shared__ float As[16][68];
    __shared__ float Bs[16][68];
    int tid = threadIdx.x;
    int tx = tid & 15, ty = tid >> 4;
    int bm = blockIdx.y * 64, bn = blockIdx.x * 64;
    int arow = tid >> 2, ac4 = tid & 3;
    int bnc = tid & 63, bkr = tid >> 6;
    float acc[4][4] = {};

    for (int k0 = 0; k0 < K; k0 += 16) {
        float4 a4 = *(const float4*)(A + (size_t)(bm + arow)*lda + k0 + ac4*4);
        As[ac4*4+0][arow] = a4.x; As[ac4*4+1][arow] = a4.y;
        As[ac4*4+2][arow] = a4.z; As[ac4*4+3][arow] = a4.w;
        #pragma unroll
        for (int p = 0; p < 4; p++)
            Bs[bkr + p*4][bnc] = Bm[(size_t)(k0 + bkr + p*4)*ldb + bn + bnc];
        __syncthreads();
        #pragma unroll
        for (int kk = 0; kk < 16; kk++) {
            float4 a = *(const float4*)&As[kk][ty*4];
            float4 b = *(const float4*)&Bs[kk][tx*4];
            float ar[4] = {a.x,a.y,a.z,a.w};
            float br[4] = {b.x,b.y,b.z,b.w};
            #pragma unroll
            for (int i = 0; i < 4; i++)
                #pragma unroll
                for (int j = 0; j < 4; j++)
                    acc[i][j] += ar[i]*br[j];
        }
        __syncthreads();
    }
    float bv[4] = {0,0,0,0};
    if (bias) {
        #pragma unroll
        for (int j = 0; j < 4; j++) bv[j] = bias[bn + tx*4 + j];
    }
    #pragma unroll
    for (int i = 0; i < 4; i++) {
        float o[4];
        #pragma unroll
        for (int j = 0; j < 4; j++) {
            float v = acc[i][j] + bv[j];
            if (epi == 1) v = gelu_exact(v);
            o[j] = v;
        }
        *(float4*)(C + (size_t)(bm + ty*4 + i)*ldc + bn + tx*4) =
            make_float4(o[0], o[1], o[2], o[3]);
    }
}

// ---------------- scores: S[b,h,q,k] = (Q.K^T)/8 + mask ----------------
__global__ __launch_bounds__(256)
void scores_kernel(const float* __restrict__ qkv,
                   const float* __restrict__ mask,   // per-batch [S,S] or null
                   float* __restrict__ scores)
{
    int z = blockIdx.z;
    int b = z / NHH, h = z % NHH;
    const float* Qb = qkv + (size_t)b*SS*1536 + h*DHH;
    const float* Kb = Qb + HH;
    float* Cb = scores + (size_t)z*SS*SS;
    const float* mb = mask ? (mask + (size_t)b*SS*SS) : nullptr;

    __shared__ float As[16][68];   // As[kk][q]
    __shared__ float Bs[16][68];   // Bs[kk][k]
    int tid = threadIdx.x;
    int tx = tid & 15, ty = tid >> 4;
    int bm = blockIdx.y * 64, bn = blockIdx.x * 64;
    int arow = tid >> 2, ac4 = tid & 3;
    float acc[4][4] = {};

    for (int k0 = 0; k0 < DHH; k0 += 16) {
        float4 a4 = *(const float4*)(Qb + (size_t)(bm + arow)*1536 + k0 + ac4*4);
        As[ac4*4+0][arow] = a4.x; As[ac4*4+1][arow] = a4.y;
        As[ac4*4+2][arow] = a4.z; As[ac4*4+3][arow] = a4.w;
        float4 b4 = *(const float4*)(Kb + (size_t)(bn + arow)*1536 + k0 + ac4*4);
        Bs[ac4*4+0][arow] = b4.x; Bs[ac4*4+1][arow] = b4.y;
        Bs[ac4*4+2][arow] = b4.z; Bs[ac4*4+3][arow] = b4.w;
        __syncthreads();
        #pragma unroll
        for (int kk = 0; kk < 16; kk++) {
            float4 a = *(const float4*)&As[kk][ty*4];
            float4 b = *(const float4*)&Bs[kk][tx*4];
            float ar[4] = {a.x,a.y,a.z,a.w};
            float br[4] = {b.x,b.y,b.z,b.w};
            #pragma unroll
            for (int i = 0; i < 4; i++)
                #pragma unroll
                for (int j = 0; j < 4; j++)
                    acc[i][j] += ar[i]*br[j];
        }
        __syncthreads();
    }
    #pragma unroll
    for (int i = 0; i < 4; i++) {
        int q = bm + ty*4 + i;
        float o[4];
        #pragma unroll
        for (int j = 0; j < 4; j++) {
            int kidx = bn + tx*4 + j;
            float v = acc[i][j] * 0.125f;
            if (mb) v += mb[(size_t)q*SS + kidx];
            o[j] = v;
        }
        *(float4*)(Cb + (size_t)q*SS + bn + tx*4) = make_float4(o[0],o[1],o[2],o[3]);
    }
}

// ---------------- softmax over last dim (512) ----------------
__global__ void softmax_kernel(float* __restrict__ scores)
{
    __shared__ float red[4];
    int row = blockIdx.x, tid = threadIdx.x;
    float* p = scores + (size_t)row * SS;
    float v[4]; float mx = -1e30f;
    #pragma unroll
    for (int j = 0; j < 4; j++) { v[j] = p[tid + 128*j]; mx = fmaxf(mx, v[j]); }
    mx = warp_max(mx);
    if ((tid & 31) == 0) red[tid >> 5] = mx;
    __syncthreads();
    mx = fmaxf(fmaxf(red[0], red[1]), fmaxf(red[2], red[3]));
    __syncthreads();
    float s = 0.f;
    #pragma unroll
    for (int j = 0; j < 4; j++) { v[j] = expf(v[j] - mx); s += v[j]; }
    s = warp_sum(s);
    if ((tid & 31) == 0) red[tid >> 5] = s;
    __syncthreads();
    float inv = 1.f / (red[0]+red[1]+red[2]+red[3]);
    #pragma unroll
    for (int j = 0; j < 4; j++) p[tid + 128*j] = v[j] * inv;
}

// ---------------- PV: O[b,q,h*64+d] = sum_k P[b,h,q,k] V[b,k,h,d] ----------------
__global__ __launch_bounds__(256)
void pv_kernel(const float* __restrict__ scores,
               const float* __restrict__ qkv,
               float* __restrict__ attno)
{
    int z = blockIdx.z;
    int b = z / NHH, h = z % NHH;
    const float* Pb = scores + (size_t)z*SS*SS;
    const float* Vb = qkv + (size_t)b*SS*1536 + 2*HH + h*DHH;
    float* Cb = attno + (size_t)b*SS*HH + h*DHH;

    __shared__ float As[16][68];   // As[kk][q]
    __shared__ float Bs[16][68];   // Bs[kk][d]
    int tid = threadIdx.x;
    int tx = tid & 15, ty = tid >> 4;
    int bm = blockIdx.y * 64;
    int arow = tid >> 2, ac4 = tid & 3;
    int bnc = tid & 63, bkr = tid >> 6;
    float acc[4][4] = {};

    for (int k0 = 0; k0 < SS; k0 += 16) {
        float4 a4 = *(const float4*)(Pb + (size_t)(bm + arow)*SS + k0 + ac4*4);
        As[ac4*4+0][arow] = a4.x; As[ac4*4+1][arow] = a4.y;
        As[ac4*4+2][arow] = a4.z; As[ac4*4+3][arow] = a4.w;
        #pragma unroll
        for (int p = 0; p < 4; p++)
            Bs[bkr + p*4][bnc] = Vb[(size_t)(k0 + bkr + p*4)*1536 + bnc];
        __syncthreads();
        #pragma unroll
        for (int kk = 0; kk < 16; kk++) {
            float4 a = *(const float4*)&As[kk][ty*4];
            float4 b = *(const float4*)&Bs[kk][tx*4];
            float ar[4] = {a.x,a.y,a.z,a.w};
            float br[4] = {b.x,b.y,b.z,b.w};
            #pragma unroll
            for (int i = 0; i < 4; i++)
                #pragma unroll
                for (int j = 0; j < 4; j++)
                    acc[i][j] += ar[i]*br[j];
        }
        __syncthreads();
    }
    #pragma unroll
    for (int i = 0; i < 4; i++)
        *(float4*)(Cb + (size_t)(bm + ty*4 + i)*HH + tx*4) =
            make_float4(acc[i][0], acc[i][1], acc[i][2], acc[i][3]);
}

// ---------------- LayerNorm over 512 (+optional residual, +optional gelu) ----------------
__global__ void ln_kernel(const float* __restrict__ in, const float* __restrict__ res,
                          const float* __restrict__ g, const float* __restrict__ be,
                          float* __restrict__ out, int do_gelu)
{
    __shared__ float red[4];
    int row = blockIdx.x, tid = threadIdx.x;
    const float* ip = in + (size_t)row*HH;
    const float* rp = res ? (res + (size_t)row*HH) : nullptr;
    float v[4]; float s = 0.f;
    #pragma unroll
    for (int j = 0; j < 4; j++) {
        float x = ip[tid + 128*j];
        if (rp) x += rp[tid + 128*j];
        v[j] = x; s += x;
    }
    s = warp_sum(s);
    if ((tid & 31) == 0) red[tid >> 5] = s;
    __syncthreads();
    float mean = (red[0]+red[1]+red[2]+red[3]) * (1.f/HH);
    __syncthreads();
    float ss = 0.f;
    #pragma unroll
    for (int j = 0; j < 4; j++) { float d = v[j] - mean; ss += d*d; }
    ss = warp_sum(ss);
    if ((tid & 31) == 0) red[tid >> 5] = ss;
    __syncthreads();
    float var = (red[0]+red[1]+red[2]+red[3]) * (1.f/HH);
    float rs = rsqrtf(var + EPS);
    float* op = out + (size_t)row*HH;
    #pragma unroll
    for (int j = 0; j < 4; j++) {
        int c = tid + 128*j;
        float y = (v[j] - mean) * rs * g[c] + be[c];
        if (do_gelu) y = gelu_exact(y);
        op[c] = y;
    }
}

// ---------------- mixer: logits(3) -> softmax -> weighted combine ----------------
__global__ void mix_kernel(const float* __restrict__ mact, const float* __restrict__ W2,
                           const float* __restrict__ b2, const float* __restrict__ comb,
                           float* __restrict__ weighted)
{
    __shared__ float sl[3][4];
    __shared__ float smix[3];
    int row = blockIdx.x, tid = threadIdx.x;
    const float* mrow = mact + (size_t)row*HH;
    float l0 = 0.f, l1 = 0.f, l2 = 0.f;
    for (int d = tid; d < HH; d += 128) {
        float m = mrow[d];
        l0 += m * W2[d*3+0];
        l1 += m * W2[d*3+1];
        l2 += m * W2[d*3+2];
    }
    l0 = warp_sum(l0); l1 = warp_sum(l1); l2 = warp_sum(l2);
    int w = tid >> 5;
    if ((tid & 31) == 0) { sl[0][w] = l0; sl[1][w] = l1; sl[2][w] = l2; }
    __syncthreads();
    if (tid == 0) {
        float a0 = sl[0][0]+sl[0][1]+sl[0][2]+sl[0][3] + b2[0];
        float a1 = sl[1][0]+sl[1][1]+sl[1][2]+sl[1][3] + b2[1];
        float a2 = sl[2][0]+sl[2][1]+sl[2][2]+sl[2][3] + b2[2];
        float mx = fmaxf(a0, fmaxf(a1, a2));
        float e0 = expf(a0-mx), e1 = expf(a1-mx), e2 = expf(a2-mx);
        float inv = 1.f / (e0+e1+e2);
        smix[0] = e0*inv; smix[1] = e1*inv; smix[2] = e2*inv;
    }
    __syncthreads();
    float m0 = smix[0], m1 = smix[1], m2 = smix[2];
    const float* crow = comb + (size_t)row*(3*HH);
    float* wrow = weighted + (size_t)row*HH;
    for (int c = tid; c < HH; c += 128)
        wrow[c] = m0*crow[c] + m1*crow[HH + c] + m2*crow[2*HH + c];
}

// ---------------- launch ----------------
extern "C" void kernel_launch(void* const* d_in, const int* in_sizes, int n_in,
                              void* d_out, int out_size)
{
    const float* x          = (const float*)d_in[0];
    const float* ts         = (const float*)d_in[1];
    const float* enc_W      = (const float*)d_in[2];
    const float* enc_b      = (const float*)d_in[3];
    const float* enc_ln_g   = (const float*)d_in[4];
    const float* enc_ln_b   = (const float*)d_in[5];
    const float* qkv_W      = (const float*)d_in[6];
    const float* qkv_b      = (const float*)d_in[7];
    const float* attn_out_W = (const float*)d_in[8];
    const float* attn_out_b = (const float*)d_in[9];
    const float* mixer_W1   = (const float*)d_in[10];
    const float* mixer_b1   = (const float*)d_in[11];
    const float* mixer_ln_g = (const float*)d_in[12];
    const float* mixer_ln_b = (const float*)d_in[13];
    const float* mixer_W2   = (const float*)d_in[14];
    const float* mixer_b2   = (const float*)d_in[15];
    const float* el_qkv_W   = (const float*)d_in[16];
    const float* el_qkv_b   = (const float*)d_in[17];
    const float* el_out_W   = (const float*)d_in[18];
    const float* el_out_b   = (const float*)d_in[19];
    const float* el_ln1_g   = (const float*)d_in[20];
    const float* el_ln1_b   = (const float*)d_in[21];
    const float* el_ff_W1   = (const float*)d_in[22];
    const float* el_ff_b1   = (const float*)d_in[23];
    const float* el_ff_W2   = (const float*)d_in[24];
    const float* el_ff_b2   = (const float*)d_in[25];
    const float* el_ln2_g   = (const float*)d_in[26];
    const float* el_ln2_b   = (const float*)d_in[27];
    const float* op_W       = (const float*)d_in[28];
    const float* op_b       = (const float*)d_in[29];
    const float* op_ln_g    = (const float*)d_in[30];
    const float* op_ln_b    = (const float*)d_in[31];
    float* out = (float*)d_out;

    float* base = nullptr;
    cudaGetSymbolAddress((void**)&base, g_scratch);
    float* mask     = base + OFF_MASK;
    float* qkv      = base + OFF_QKV;
    float* scores   = base + OFF_SCORES;
    float* attno    = base + OFF_ATTNO;
    float* comb     = base + OFF_COMB;
    float* mact     = base + OFF_MACT;
    float* weighted = base + OFF_WEIGHTED;
    float* sa       = base + OFF_SA;
    float* h1       = base + OFF_H1;
    float* ff       = base + OFF_FF;
    float* ffo      = base + OFF_FFO;
    float* h2       = base + OFF_H2;
    float* opb      = base + OFF_OP;

    // 1. temporal masks (3 timescales)
    mask_kernel<<<2048, 256>>>(ts, enc_W, enc_b, enc_ln_g, enc_ln_b, mask);

    // 2. per-timescale MHA
    for (int i = 0; i < TT; i++) {
        gemm_nn<<<dim3(1536/64, BS/64), 256>>>(x, HH, qkv_W + (size_t)i*HH*1536, 1536,
                                               qkv_b + (size_t)i*1536, qkv, 1536, HH, 0);
        scores_kernel<<<dim3(8, 8, BB*NHH), 256>>>(qkv, mask + (size_t)i*BSS, scores);
        softmax_kernel<<<BB*NHH*SS, 128>>>(scores);
        pv_kernel<<<dim3(1, 8, BB*NHH), 256>>>(scores, qkv, attno);
        gemm_nn<<<dim3(HH/64, BS/64), 256>>>(attno, HH, attn_out_W + (size_t)i*HH*HH, HH,
                                             attn_out_b + (size_t)i*HH,
                                             comb + (size_t)i*HH, 1536, HH, 0);
    }

    // 3. time mixer
    gemm_nn<<<dim3(HH/64, BS/64), 256>>>(comb, 1536, mixer_W1, HH, mixer_b1, mact, HH, 1536, 0);
    ln_kernel<<<BS, 128>>>(mact, nullptr, mixer_ln_g, mixer_ln_b, mact, 1);
    mix_kernel<<<BS, 128>>>(mact, mixer_W2, mixer_b2, comb, weighted);

    // 4. transformer encoder layer (post-norm)
    gemm_nn<<<dim3(1536/64, BS/64), 256>>>(weighted, HH, el_qkv_W, 1536, el_qkv_b, qkv, 1536, HH, 0);
    scores_kernel<<<dim3(8, 8, BB*NHH), 256>>>(qkv, nullptr, scores);
    softmax_kernel<<<BB*NHH*SS, 128>>>(scores);
    pv_kernel<<<dim3(1, 8, BB*NHH), 256>>>(scores, qkv, attno);
    gemm_nn<<<dim3(HH/64, BS/64), 256>>>(attno, HH, el_out_W, HH, el_out_b, sa, HH, HH, 0);
    ln_kernel<<<BS, 128>>>(sa, weighted, el_ln1_g, el_ln1_b, h1, 0);
    gemm_nn<<<dim3(2048/64, BS/64), 256>>>(h1, HH, el_ff_W1, 2048, el_ff_b1, ff, 2048, HH, 1);
    gemm_nn<<<dim3(HH/64, BS/64), 256>>>(ff, 2048, el_ff_W2, HH, el_ff_b2, ffo, HH, 2048, 0);
    ln_kernel<<<BS, 128>>>(ffo, h1, el_ln2_g, el_ln2_b, h2, 0);

    // 5. output projection + LN
    gemm_nn<<<dim3(HH/64, BS/64), 256>>>(h2, HH, op_W, HH, op_b, opb, HH, HH, 0);
    ln_kernel<<<BS, 128>>>(opb, nullptr, op_ln_g, op_ln_b, out, 0);
}

// round 2
// speedup vs baseline: 3.0241x; 3.0241x over previous
#include <cuda_runtime.h>
#include <math.h>
#include <stdint.h>

// ---------------- problem constants ----------------
#define BB   4
#define SS   512
#define HH   512
#define NHH  8
#define TT   3
#define DHH  64
#define DTS  170
#define BS   (BB*SS)             // 2048
#define BSS  (BB*SS*SS)          // 1,048,576
#define EPS  1e-5f

// mask lookup table
#define NTAB   4096
#define M0MAX  5.6400f
#define TABENT (NTAB+1)
#define TABSZ  (3*2*TABENT + 3)

// ---------------- scratch layout (floats) ----------------
#define OFF_MASK     ((size_t)0)                         // 3 * BSS
#define OFF_QKV      (OFF_MASK + (size_t)3*BSS)          // BS * 1536
#define OFF_SCORES   (OFF_QKV + (size_t)BS*1536)         // B*NH*S*S
#define OFF_ATTNO    (OFF_SCORES + (size_t)BB*NHH*SS*SS) // BS*H
#define OFF_COMB     (OFF_ATTNO + (size_t)BS*HH)         // BS*1536
#define OFF_MACT     (OFF_COMB + (size_t)BS*1536)
#define OFF_WEIGHTED (OFF_MACT + (size_t)BS*HH)
#define OFF_SA       (OFF_WEIGHTED + (size_t)BS*HH)
#define OFF_H1       (OFF_SA + (size_t)BS*HH)
#define OFF_FF       (OFF_H1 + (size_t)BS*HH)            // BS*2048
#define OFF_FFO      (OFF_FF + (size_t)BS*2048)
#define OFF_H2       (OFF_FFO + (size_t)BS*HH)
#define OFF_OP       (OFF_H2 + (size_t)BS*HH)
#define OFF_TAB      (OFF_OP + (size_t)BS*HH)
#define SCRATCH_FLOATS (OFF_TAB + (size_t)TABSZ)

__device__ float g_scratch[SCRATCH_FLOATS];

// ---------------- helpers ----------------
__device__ __forceinline__ float gelu_exact(float x) {
    return 0.5f * x * (1.0f + erff(x * 0.70710678118654752f));
}
__device__ __forceinline__ float warp_sum(float x) {
    #pragma unroll
    for (int o = 16; o > 0; o >>= 1) x += __shfl_xor_sync(0xffffffffu, x, o);
    return x;
}
__device__ __forceinline__ float warp_max(float x) {
    #pragma unroll
    for (int o = 16; o > 0; o >>= 1) x = fmaxf(x, __shfl_xor_sync(0xffffffffu, x, o));
    return x;
}
__device__ __forceinline__ float to_tf32(float x) {
    uint32_t u;
    asm("cvt.rna.tf32.f32 %0, %1;" : "=r"(u) : "f"(x));
    return __uint_as_float(u);
}
__device__ __forceinline__ void mma_tf32(float* c, const float* a, const float* b) {
    asm volatile(
        "mma.sync.aligned.m16n8k8.row.col.f32.tf32.tf32.f32 "
        "{%0,%1,%2,%3}, {%4,%5,%6,%7}, {%8,%9}, {%0,%1,%2,%3};\n"
        : "+f"(c[0]), "+f"(c[1]), "+f"(c[2]), "+f"(c[3])
        : "r"(__float_as_uint(a[0])), "r"(__float_as_uint(a[1])),
          "r"(__float_as_uint(a[2])), "r"(__float_as_uint(a[3])),
          "r"(__float_as_uint(b[0])), "r"(__float_as_uint(b[1])));
}

// ---------------- mask table build ----------------
// one warp per (timescale, dir, mag-grid-node) entry + 3 diagonal entries
__global__ void tab_kernel(const float* __restrict__ enc_W,
                           const float* __restrict__ enc_b,
                           const float* __restrict__ enc_g,
                           const float* __restrict__ enc_be,
                           float* __restrict__ tab)
{
    int w = (blockIdx.x * blockDim.x + threadIdx.x) >> 5;
    int lane = threadIdx.x & 31;
    const int NE = 3 * 2 * TABENT;
    if (w >= NE + 3) return;
    int i; float dir, mag;
    if (w < NE) {
        i = w / (2 * TABENT);
        int r = w - i * (2 * TABENT);
        int d = r / TABENT;
        int j = r - d * TABENT;
        dir = d ? 1.f : -1.f;
        float m0 = (float)j * (M0MAX / NTAB);
        float sc = (i == 0) ? 1.f : ((i == 1) ? 0.1f : 0.01f);
        mag = m0 * sc;
    } else {
        i = w - NE; dir = 0.f; mag = 0.f;
    }
    const float* W0 = enc_W + (size_t)(i*2+0)*DTS;
    const float* W1 = enc_W + (size_t)(i*2+1)*DTS;
    const float* bb = enc_b + (size_t)i*DTS;
    const float* gg = enc_g + (size_t)i*DTS;
    const float* be = enc_be + (size_t)i*DTS;

    float e[6];
    float s = 0.f, ss = 0.f;
    #pragma unroll
    for (int j2 = 0; j2 < 6; j2++) {
        int d = lane + 32*j2;
        float v = 0.f;
        if (d < DTS) v = dir*W0[d] + mag*W1[d] + bb[d];
        e[j2] = v; s += v; ss += v*v;
    }
    s  = warp_sum(s);
    ss = warp_sum(ss);
    float mean = s * (1.f/DTS);
    float var  = ss * (1.f/DTS) - mean*mean;
    float rs = rsqrtf(var + EPS);
    float gs = 0.f;
    #pragma unroll
    for (int j2 = 0; j2 < 6; j2++) {
        int d = lane + 32*j2;
        if (d < DTS) {
            float y = (e[j2] - mean) * rs * gg[d] + be[d];
            gs += gelu_exact(y);
        }
    }
    gs = warp_sum(gs);
    if (lane == 0) tab[w] = gs * (1.f/DTS);
}

// ---------------- mask fill via table interpolation ----------------
__global__ void maskfill_kernel(const float* __restrict__ ts,
                                const float* __restrict__ tab,
                                float* __restrict__ masks)
{
    int idx = blockIdx.x * blockDim.x + threadIdx.x;
    if (idx >= BSS) return;
    int b = idx >> 18;
    int q = (idx >> 9) & 511;
    int k = idx & 511;
    float dt = ts[(b << 9) + q] - ts[(b << 9) + k];
    if (dt == 0.f) {
        #pragma unroll
        for (int i = 0; i < TT; i++)
            masks[(size_t)i*BSS + idx] = tab[3*2*TABENT + i];
    } else {
        int d = dt > 0.f ? 1 : 0;
        float m0 = log1pf(fabsf(dt) * (1.f/3600.f));
        float t = m0 * ((float)NTAB / M0MAX);
        t = fminf(t, (float)NTAB - 1e-3f);
        int j = (int)t;
        float f = t - (float)j;
        #pragma unroll
        for (int i = 0; i < TT; i++) {
            const float* tb = tab + (size_t)(i*2 + d) * TABENT;
            float a = tb[j];
            masks[(size_t)i*BSS + idx] = a + f * (tb[j+1] - a);
        }
    }
}

// ---------------- tf32 tensor-core GEMM ----------------
// C[M,N] = A[M,K] @ B (+ epilogue). BM=128 fixed, BK=16, 8 warps (2x4).
// MODE 0: plain NN gemm, bias add, optional exact GELU. grid (N/BN, M/128, 1)
// MODE 1: scores  — A=Q, B=K (NT, from packed qkv), *0.125 + optional mask.
//                   grid (512/128, 512/128, B*NH). BN must be 128.
// MODE 2: pv      — A=P (NN), B=V strided from packed qkv. grid (64/BN, 4, B*NH)
template<int BN, int MODE, int GELU>
__global__ __launch_bounds__(256)
void gemm_tc(const float* __restrict__ A0, int lda,
             const float* __restrict__ B0, int ldb,
             const float* __restrict__ bias,
             float* __restrict__ C0, int ldc, int K,
             const float* __restrict__ mask)
{
    constexpr int BM = 128;
    constexpr int BK = 16;
    constexpr bool TB = (MODE == 1);
    constexpr int WN = BN / 4;        // warp tile N
    constexpr int NT2 = WN / 8;       // n-tiles per warp
    constexpr int BROWS = TB ? BN : BK;
    constexpr int BCOLS = TB ? (BK + 4) : (BN + 8);

    __shared__ float sA[2][BM][BK + 4];
    __shared__ float sB[2][BROWS][BCOLS];

    const int tid  = threadIdx.x;
    const int lane = tid & 31;
    const int warp = tid >> 5;
    const int wm = warp & 1;
    const int wn = warp >> 1;
    const int g = lane >> 2;
    const int c = lane & 3;

    const int bm = blockIdx.y * BM;
    const int bn = blockIdx.x * BN;

    const float* A = A0;
    const float* B = B0;
    float* C = C0;
    const float* mbase = nullptr;
    if (MODE == 1) {
        int z = blockIdx.z, b = z >> 3, h = z & 7;
        A = A0 + (size_t)b*SS*1536 + h*DHH;
        B = A + HH;
        C = C0 + (size_t)z*SS*SS;
        if (mask) mbase = mask + (size_t)b*SS*SS;
    } else if (MODE == 2) {
        int z = blockIdx.z, b = z >> 3, h = z & 7;
        A = A0 + (size_t)z*SS*SS;
        B = B0 + (size_t)b*SS*1536 + 2*HH + h*DHH;
        C = C0 + (size_t)b*SS*HH + h*DHH;
    }

    // A staging: [BM][BK] tile, float4 per thread along K, m-major smem
    const int ar = tid >> 2;
    const int ac = (tid & 3) * 4;
    const float* aP  = A + (size_t)(bm + ar)*lda + ac;
    const float* aP2 = aP + (size_t)64*lda;

    // B staging indices
    int br, bc;
    if (TB)              { br = tid >> 2; bc = (tid & 3) * 4; }
    else if (BN == 128)  { br = tid >> 5; bc = (tid & 31) * 4; }
    else                 { br = tid >> 4; bc = (tid & 15) * 4; }

    float acc[4][NT2][4];
    #pragma unroll
    for (int i = 0; i < 4; i++)
        #pragma unroll
        for (int j = 0; j < NT2; j++)
            #pragma unroll
            for (int q = 0; q < 4; q++) acc[i][j][q] = 0.f;

    auto loadB = [&](int k0, float4& x, float4& y) {
        if constexpr (TB) {
            const float* p = B + (size_t)(bn + br)*ldb + bc + k0;
            x = *(const float4*)p;
            y = *(const float4*)(p + (size_t)64*ldb);
        } else if constexpr (BN == 128) {
            const float* p = B + (size_t)(k0 + br)*ldb + bn + bc;
            x = *(const float4*)p;
            y = *(const float4*)(p + (size_t)8*ldb);
        } else {
            const float* p = B + (size_t)(k0 + br)*ldb + bn + bc;
            x = *(const float4*)p;
            y = make_float4(0.f,0.f,0.f,0.f);
        }
    };
    auto storeB = [&](int buf, float4 x, float4 y) {
        if constexpr (TB) {
            sB[buf][br][bc+0] = to_tf32(x.x); sB[buf][br][bc+1] = to_tf32(x.y);
            sB[buf][br][bc+2] = to_tf32(x.z); sB[buf][br][bc+3] = to_tf32(x.w);
            sB[buf][br+64][bc+0] = to_tf32(y.x); sB[buf][br+64][bc+1] = to_tf32(y.y);
            sB[buf][br+64][bc+2] = to_tf32(y.z); sB[buf][br+64][bc+3] = to_tf32(y.w);
        } else if constexpr (BN == 128) {
            sB[buf][br][bc+0] = to_tf32(x.x); sB[buf][br][bc+1] = to_tf32(x.y);
            sB[buf][br][bc+2] = to_tf32(x.z); sB[buf][br][bc+3] = to_tf32(x.w);
            sB[buf][br+8][bc+0] = to_tf32(y.x); sB[buf][br+8][bc+1] = to_tf32(y.y);
            sB[buf][br+8][bc+2] = to_tf32(y.z); sB[buf][br+8][bc+3] = to_tf32(y.w);
        } else {
            sB[buf][br][bc+0] = to_tf32(x.x); sB[buf][br][bc+1] = to_tf32(x.y);
            sB[buf][br][bc+2] = to_tf32(x.z); sB[buf][br][bc+3] = to_tf32(x.w);
        }
    };

    const int nstage = K / BK;
    float4 pa0, pa1, pb0, pb1;

    pa0 = *(const float4*)(aP);
    pa1 = *(const float4*)(aP2);
    loadB(0, pb0, pb1);
    sA[0][ar][ac+0] = to_tf32(pa0.x); sA[0][ar][ac+1] = to_tf32(pa0.y);
    sA[0][ar][ac+2] = to_tf32(pa0.z); sA[0][ar][ac+3] = to_tf32(pa0.w);
    sA[0][ar+64][ac+0] = to_tf32(pa1.x); sA[0][ar+64][ac+1] = to_tf32(pa1.y);
    sA[0][ar+64][ac+2] = to_tf32(pa1.z); sA[0][ar+64][ac+3] = to_tf32(pa1.w);
    storeB(0, pb0, pb1);
    __syncthreads();

    for (int s = 0; s < nstage; s++) {
        const int cur = s & 1;
        const bool more = (s + 1 < nstage);
        if (more) {
            const int k0 = (s + 1) * BK;
            pa0 = *(const float4*)(aP + k0);
            pa1 = *(const float4*)(aP2 + k0);
            loadB(k0, pb0, pb1);
        }
        #pragma unroll
        for (int kk = 0; kk < 2; kk++) {
            const int kb = kk * 8;
            float af[4][4];
            #pragma unroll
            for (int mt = 0; mt < 4; mt++) {
                const int r0 = wm*64 + mt*16 + g;
                af[mt][0] = sA[cur][r0][kb + c];
                af[mt][1] = sA[cur][r0 + 8][kb + c];
                af[mt][2] = sA[cur][r0][kb + c + 4];
                af[mt][3] = sA[cur][r0 + 8][kb + c + 4];
            }
            float bf[NT2][2];
            #pragma unroll
            for (int nt = 0; nt < NT2; nt++) {
                const int n0 = wn*WN + nt*8 + g;
                if constexpr (TB) {
                    bf[nt][0] = sB[cur][n0][kb + c];
                    bf[nt][1] = sB[cur][n0][kb + c + 4];
                } else {
                    bf[nt][0] = sB[cur][kb + c][n0];
                    bf[nt][1] = sB[cur][kb + c + 4][n0];
                }
            }
            #pragma unroll
            for (int mt = 0; mt < 4; mt++)
                #pragma unroll
                for (int nt = 0; nt < NT2; nt++)
                    mma_tf32(acc[mt][nt], af[mt], bf[nt]);
        }
        if (more) {
            const int nxt = cur ^ 1;
            sA[nxt][ar][ac+0] = to_tf32(pa0.x); sA[nxt][ar][ac+1] = to_tf32(pa0.y);
            sA[nxt][ar][ac+2] = to_tf32(pa0.z); sA[nxt][ar][ac+3] = to_tf32(pa0.w);
            sA[nxt][ar+64][ac+0] = to_tf32(pa1.x); sA[nxt][ar+64][ac+1] = to_tf32(pa1.y);
            sA[nxt][ar+64][ac+2] = to_tf32(pa1.z); sA[nxt][ar+64][ac+3] = to_tf32(pa1.w);
            storeB(nxt, pb0, pb1);
        }
        __syncthreads();
    }

    // epilogue
    #pragma unroll
    for (int mt = 0; mt < 4; mt++) {
        const int row = bm + wm*64 + mt*16 + g;
        #pragma unroll
        for (int nt = 0; nt < NT2; nt++) {
            const int col = bn + wn*WN + nt*8 + c*2;
            float v00 = acc[mt][nt][0], v01 = acc[mt][nt][1];
            float v10 = acc[mt][nt][2], v11 = acc[mt][nt][3];
            if constexpr (MODE == 1) {
                v00 *= 0.125f; v01 *= 0.125f; v10 *= 0.125f; v11 *= 0.125f;
                if (mbase) {
                    float2 m0 = *(const float2*)(mbase + (size_t)row*SS + col);
                    float2 m1 = *(const float2*)(mbase + (size_t)(row+8)*SS + col);
                    v00 += m0.x; v01 += m0.y; v10 += m1.x; v11 += m1.y;
                }
            }
            if constexpr (MODE == 0) {
                float2 bb = *(const float2*)(bias + col);
                v00 += bb.x; v01 += bb.y; v10 += bb.x; v11 += bb.y;
                if constexpr (GELU) {
                    v00 = gelu_exact(v00); v01 = gelu_exact(v01);
                    v10 = gelu_exact(v10); v11 = gelu_exact(v11);
                }
            }
            *(float2*)(C + (size_t)row*ldc + col) = make_float2(v00, v01);
            *(float2*)(C + (size_t)(row+8)*ldc + col) = make_float2(v10, v11);
        }
    }
}

// ---------------- softmax over last dim (512) ----------------
__global__ void softmax_kernel(float* __restrict__ scores)
{
    __shared__ float red[4];
    int row = blockIdx.x, tid = threadIdx.x;
    float* p = scores + (size_t)row * SS;
    float v[4]; float mx = -1e30f;
    #pragma unroll
    for (int j = 0; j < 4; j++) { v[j] = p[tid + 128*j]; mx = fmaxf(mx, v[j]); }
    mx = warp_max(mx);
    if ((tid & 31) == 0) red[tid >> 5] = mx;
    __syncthreads();
    mx = fmaxf(fmaxf(red[0], red[1]), fmaxf(red[2], red[3]));
    __syncthreads();
    float s = 0.f;
    #pragma unroll
    for (int j = 0; j < 4; j++) { v[j] = expf(v[j] - mx); s += v[j]; }
    s = warp_sum(s);
    if ((tid & 31) == 0) red[tid >> 5] = s;
    __syncthreads();
    float inv = 1.f / (red[0]+red[1]+red[2]+red[3]);
    #pragma unroll
    for (int j = 0; j < 4; j++) p[tid + 128*j] = v[j] * inv;
}

// ---------------- LayerNorm over 512 (+optional residual, +optional gelu) ----------------
__global__ void ln_kernel(const float* __restrict__ in, const float* __restrict__ res,
                          const float* __restrict__ g, const float* __restrict__ be,
                          float* __restrict__ out, int do_gelu)
{
    __shared__ float red[4];
    int row = blockIdx.x, tid = threadIdx.x;
    const float* ip = in + (size_t)row*HH;
    const float* rp = res ? (res + (size_t)row*HH) : nullptr;
    float v[4]; float s = 0.f;
    #pragma unroll
    for (int j = 0; j < 4; j++) {
        float x = ip[tid + 128*j];
        if (rp) x += rp[tid + 128*j];
        v[j] = x; s += x;
    }
    s = warp_sum(s);
    if ((tid & 31) == 0) red[tid >> 5] = s;
    __syncthreads();
    float mean = (red[0]+red[1]+red[2]+red[3]) * (1.f/HH);
    __syncthreads();
    float ss = 0.f;
    #pragma unroll
    for (int j = 0; j < 4; j++) { float d = v[j] - mean; ss += d*d; }
    ss = warp_sum(ss);
    if ((tid & 31) == 0) red[tid >> 5] = ss;
    __syncthreads();
    float var = (red[0]+red[1]+red[2]+red[3]) * (1.f/HH);
    float rs = rsqrtf(var + EPS);
    float* op = out + (size_t)row*HH;
    #pragma unroll
    for (int j = 0; j < 4; j++) {
        int c = tid + 128*j;
        float y = (v[j] - mean) * rs * g[c] + be[c];
        if (do_gelu) y = gelu_exact(y);
        op[c] = y;
    }
}

// ---------------- mixer: logits(3) -> softmax -> weighted combine ----------------
__global__ void mix_kernel(const float* __restrict__ mact, const float* __restrict__ W2,
                           const float* __restrict__ b2, const float* __restrict__ comb,
                           float* __restrict__ weighted)
{
    __shared__ float sl[3][4];
    __shared__ float smix[3];
    int row = blockIdx.x, tid = threadIdx.x;
    const float* mrow = mact + (size_t)row*HH;
    float l0 = 0.f, l1 = 0.f, l2 = 0.f;
    for (int d = tid; d < HH; d += 128) {
        float m = mrow[d];
        l0 += m * W2[d*3+0];
        l1 += m * W2[d*3+1];
        l2 += m * W2[d*3+2];
    }
    l0 = warp_sum(l0); l1 = warp_sum(l1); l2 = warp_sum(l2);
    int w = tid >> 5;
    if ((tid & 31) == 0) { sl[0][w] = l0; sl[1][w] = l1; sl[2][w] = l2; }
    __syncthreads();
    if (tid == 0) {
        float a0 = sl[0][0]+sl[0][1]+sl[0][2]+sl[0][3] + b2[0];
        float a1 = sl[1][0]+sl[1][1]+sl[1][2]+sl[1][3] + b2[1];
        float a2 = sl[2][0]+sl[2][1]+sl[2][2]+sl[2][3] + b2[2];
        float mx = fmaxf(a0, fmaxf(a1, a2));
        float e0 = expf(a0-mx), e1 = expf(a1-mx), e2 = expf(a2-mx);
        float inv = 1.f / (e0+e1+e2);
        smix[0] = e0*inv; smix[1] = e1*inv; smix[2] = e2*inv;
    }
    __syncthreads();
    float m0 = smix[0], m1 = smix[1], m2 = smix[2];
    const float* crow = comb + (size_t)row*(3*HH);
    float* wrow = weighted + (size_t)row*HH;
    for (int c = tid; c < HH; c += 128)
        wrow[c] = m0*crow[c] + m1*crow[HH + c] + m2*crow[2*HH + c];
}

// ---------------- launch ----------------
extern "C" void kernel_launch(void* const* d_in, const int* in_sizes, int n_in,
                              void* d_out, int out_size)
{
    const float* x          = (const float*)d_in[0];
    const float* ts         = (const float*)d_in[1];
    const float* enc_W      = (const float*)d_in[2];
    const float* enc_b      = (const float*)d_in[3];
    const float* enc_ln_g   = (const float*)d_in[4];
    const float* enc_ln_b   = (const float*)d_in[5];
    const float* qkv_W      = (const float*)d_in[6];
    const float* qkv_b      = (const float*)d_in[7];
    const float* attn_out_W = (const float*)d_in[8];
    const float* attn_out_b = (const float*)d_in[9];
    const float* mixer_W1   = (const float*)d_in[10];
    const float* mixer_b1   = (const float*)d_in[11];
    const float* mixer_ln_g = (const float*)d_in[12];
    const float* mixer_ln_b = (const float*)d_in[13];
    const float* mixer_W2   = (const float*)d_in[14];
    const float* mixer_b2   = (const float*)d_in[15];
    const float* el_qkv_W   = (const float*)d_in[16];
    const float* el_qkv_b   = (const float*)d_in[17];
    const float* el_out_W   = (const float*)d_in[18];
    const float* el_out_b   = (const float*)d_in[19];
    const float* el_ln1_g   = (const float*)d_in[20];
    const float* el_ln1_b   = (const float*)d_in[21];
    const float* el_ff_W1   = (const float*)d_in[22];
    const float* el_ff_b1   = (const float*)d_in[23];
    const float* el_ff_W2   = (const float*)d_in[24];
    const float* el_ff_b2   = (const float*)d_in[25];
    const float* el_ln2_g   = (const float*)d_in[26];
    const float* el_ln2_b   = (const float*)d_in[27];
    const float* op_W       = (const float*)d_in[28];
    const float* op_b       = (const float*)d_in[29];
    const float* op_ln_g    = (const float*)d_in[30];
    const float* op_ln_b    = (const float*)d_in[31];
    float* out = (float*)d_out;

    float* base = nullptr;
    cudaGetSymbolAddress((void**)&base, g_scratch);
    float* maskv    = base + OFF_MASK;
    float* qkv      = base + OFF_QKV;
    float* scores   = base + OFF_SCORES;
    float* attno    = base + OFF_ATTNO;
    float* comb     = base + OFF_COMB;
    float* mact     = base + OFF_MACT;
    float* weighted = base + OFF_WEIGHTED;
    float* sa       = base + OFF_SA;
    float* h1       = base + OFF_H1;
    float* ff       = base + OFF_FF;
    float* ffo      = base + OFF_FFO;
    float* h2       = base + OFF_H2;
    float* opb      = base + OFF_OP;
    float* tab      = base + OFF_TAB;

    // 1. mask tables + fill
    {
        int nwarp = 3*2*TABENT + 3;
        int nblk = (nwarp*32 + 255) / 256;
        tab_kernel<<<nblk, 256>>>(enc_W, enc_b, enc_ln_g, enc_ln_b, tab);
        maskfill_kernel<<<(BSS + 255)/256, 256>>>(ts, tab, maskv);
    }

    // 2. per-timescale MHA
    for (int i = 0; i < TT; i++) {
        gemm_tc<128,0,0><<<dim3(12,16,1), 256>>>(x, HH, qkv_W + (size_t)i*HH*1536, 1536,
                                                 qkv_b + (size_t)i*1536, qkv, 1536, HH, nullptr);
        gemm_tc<128,1,0><<<dim3(4,4,BB*NHH), 256>>>(qkv, 1536, qkv, 1536, nullptr,
                                                    scores, SS, DHH, maskv + (size_t)i*BSS);
        softmax_kernel<<<BB*NHH*SS, 128>>>(scores);
        gemm_tc<64,2,0><<<dim3(1,4,BB*NHH), 256>>>(scores, SS, qkv, 1536, nullptr,
                                                   attno, HH, SS, nullptr);
        gemm_tc<64,0,0><<<dim3(8,16,1), 256>>>(attno, HH, attn_out_W + (size_t)i*HH*HH, HH,
                                               attn_out_b + (size_t)i*HH,
                                               comb + (size_t)i*HH, 1536, HH, nullptr);
    }

    // 3. time mixer
    gemm_tc<64,0,0><<<dim3(8,16,1), 256>>>(comb, 1536, mixer_W1, HH, mixer_b1, mact, HH, 1536, nullptr);
    ln_kernel<<<BS, 128>>>(mact, nullptr, mixer_ln_g, mixer_ln_b, mact, 1);
    mix_kernel<<<BS, 128>>>(mact, mixer_W2, mixer_b2, comb, weighted);

    // 4. transformer encoder layer (post-norm)
    gemm_tc<128,0,0><<<dim3(12,16,1), 256>>>(weighted, HH, el_qkv_W, 1536, el_qkv_b, qkv, 1536, HH, nullptr);
    gemm_tc<128,1,0><<<dim3(4,4,BB*NHH), 256>>>(qkv, 1536, qkv, 1536, nullptr, scores, SS, DHH, nullptr);
    softmax_kernel<<<BB*NHH*SS, 128>>>(scores);
    gemm_tc<64,2,0><<<dim3(1,4,BB*NHH), 256>>>(scores, SS, qkv, 1536, nullptr, attno, HH, SS, nullptr);
    gemm_tc<64,0,0><<<dim3(8,16,1), 256>>>(attno, HH, el_out_W, HH, el_out_b, sa, HH, HH, nullptr);
    ln_kernel<<<BS, 128>>>(sa, weighted, el_ln1_g, el_ln1_b, h1, 0);
    gemm_tc<128,0,1><<<dim3(16,16,1), 256>>>(h1, HH, el_ff_W1, 2048, el_ff_b1, ff, 2048, HH, nullptr);
    gemm_tc<64,0,0><<<dim3(8,16,1), 256>>>(ff, 2048, el_ff_W2, HH, el_ff_b2, ffo, HH, 2048, nullptr);
    ln_kernel<<<BS, 128>>>(ffo, h1, el_ln2_g, el_ln2_b, h2, 0);

    // 5. output projection + LN
    gemm_tc<64,0,0><<<dim3(8,16,1), 256>>>(h2, HH, op_W, HH, op_b, opb, HH, HH, nullptr);
    ln_kernel<<<BS, 128>>>(opb, nullptr, op_ln_g, op_ln_b, out, 0);
}